// round 1
// baseline (speedup 1.0000x reference)
#include <cuda_runtime.h>

// Problem constants
#define N_U   1024      // IN_U == OUT_U
#define BATCH 4096
#define H     10        // MLP hidden width
#define INV1023 (1.0f / 1023.0f)

// ---------------------------------------------------------------------------
// Scratch (device globals; no allocation allowed)
// ---------------------------------------------------------------------------
__device__ float g_colpart[32][N_U];      // partial column sums (deterministic 2-stage)
__device__ float g_colsum[N_U];
__device__ float g_rowsum[N_U];
__device__ float g_F[N_U][H];             // i-dependent layer-1 contribution
__device__ float g_G[N_U][H];             // j-dependent layer-1 contribution (+consts +b1)
__device__ float g_ACR[3][H];             // A (coeff of w), C (coeff of colsum), R (coeff of rowsum)
__device__ float g_NW[N_U * N_U];         // new_weight

// ---------------------------------------------------------------------------
// Column sums of weight (two deterministic stages, no atomics)
// ---------------------------------------------------------------------------
__global__ void __launch_bounds__(128) colpart_kernel(const float* __restrict__ W) {
    int col = blockIdx.x * 128 + threadIdx.x;   // gridDim.x = 8
    int r0  = blockIdx.y * 32;                  // gridDim.y = 32
    float s = 0.f;
#pragma unroll
    for (int r = 0; r < 32; r++) s += W[(r0 + r) * N_U + col];
    g_colpart[blockIdx.y][col] = s;
}

__global__ void __launch_bounds__(256) colsum_kernel() {
    int col = blockIdx.x * 256 + threadIdx.x;   // gridDim.x = 4
    float s = 0.f;
#pragma unroll
    for (int b = 0; b < 32; b++) s += g_colpart[b][col];
    g_colsum[col] = s;
}

// ---------------------------------------------------------------------------
// Row sums of weight
// ---------------------------------------------------------------------------
__global__ void __launch_bounds__(256) rowsum_kernel(const float* __restrict__ W) {
    __shared__ float red[8];
    int row = blockIdx.x;
    int tid = threadIdx.x;
    float4 v = *(const float4*)(W + row * N_U + tid * 4);
    float s = v.x + v.y + v.z + v.w;
#pragma unroll
    for (int o = 16; o > 0; o >>= 1) s += __shfl_xor_sync(0xffffffffu, s, o);
    if ((tid & 31) == 0) red[tid >> 5] = s;
    __syncthreads();
    if (tid == 0) {
        float t = 0.f;
#pragma unroll
        for (int i = 0; i < 8; i++) t += red[i];
        g_rowsum[row] = t;
    }
}

// ---------------------------------------------------------------------------
// Precompute per-i (F), per-j (G), and scalar coefficient tables from W1/b1.
// hidden[i,j,t] = bit(9-t) of i  (t<10),  bit(19-t) of j  (t>=10)
// fwd_hs[t<10]  = (512 - bit_i)/1023 ; fwd_hs[t>=10] = bit_j (exactly)
// bwd_hs[t<10]  = bit_i            ; bwd_hs[t>=10] = (512 - bit_j)/1023
// ---------------------------------------------------------------------------
__global__ void precompute_kernel(const float* __restrict__ W1,
                                  const float* __restrict__ b1) {
    int idx = blockIdx.x * blockDim.x + threadIdx.x;
    if (idx < N_U) {
        int i = idx;
#pragma unroll
        for (int h = 0; h < H; h++) {
            float acc = 0.f;
#pragma unroll
            for (int t = 0; t < 10; t++) {
                float coef = W1[(3 + t) * H + h] + W1[(43 + t) * H + h]
                           - W1[(23 + t) * H + h] * INV1023;
                if ((i >> (9 - t)) & 1) acc += coef;
            }
            g_F[i][h] = acc;
        }
    } else if (idx < 2 * N_U) {
        int j = idx - N_U;
#pragma unroll
        for (int h = 0; h < H; h++) {
            float acc = b1[h];
#pragma unroll
            for (int s = 0; s < 10; s++) {
                float coef = W1[(13 + s) * H + h] + W1[(33 + s) * H + h]
                           - W1[(53 + s) * H + h] * INV1023;
                if ((j >> (9 - s)) & 1) acc += coef;
                acc += (512.f * INV1023) * (W1[(23 + s) * H + h] + W1[(53 + s) * H + h]);
            }
            g_G[j][h] = acc;
        }
    } else if (idx < 2 * N_U + H) {
        int h = idx - 2 * N_U;
        g_ACR[0][h] = W1[h] - (W1[H + h] + W1[2 * H + h]) * INV1023;  // coeff of w
        g_ACR[1][h] = W1[H + h] * INV1023;                            // coeff of colsum_j
        g_ACR[2][h] = W1[2 * H + h] * INV1023;                        // coeff of rowsum_i
    }
}

// ---------------------------------------------------------------------------
// Per-cell MLP -> new_weight.  One block per row i; 4 columns per thread.
// ---------------------------------------------------------------------------
__global__ void __launch_bounds__(256) mlp_kernel(const float* __restrict__ W,
                                                  const float* __restrict__ W2,
                                                  const float* __restrict__ b2,
                                                  const float* __restrict__ W3,
                                                  const float* __restrict__ b3) {
    __shared__ float sW2[H * H], sB2[H], sW3[H], sF[H];
    __shared__ float sA[H], sC[H], sR[H];
    __shared__ float sb3;
    int tid = threadIdx.x;
    int i = blockIdx.x;
    if (tid < H * H) sW2[tid] = W2[tid];
    if (tid < H) {
        sB2[tid] = b2[tid];
        sW3[tid] = W3[tid * 21];          // only output column 0 matters
        sF[tid]  = g_F[i][tid];
        sA[tid]  = g_ACR[0][tid];
        sC[tid]  = g_ACR[1][tid];
        sR[tid]  = g_ACR[2][tid];
    }
    if (tid == 0) sb3 = b3[0];
    __syncthreads();

    float rs = g_rowsum[i];
#pragma unroll
    for (int c = 0; c < 4; c++) {
        int j = c * 256 + tid;
        float w  = W[i * N_U + j];
        float cs = g_colsum[j];
        float z[H];
#pragma unroll
        for (int h = 0; h < H; h++) {
            float v = fmaf(sA[h], w, fmaf(sC[h], cs, fmaf(sR[h], rs, sF[h] + g_G[j][h])));
            z[h] = fmaxf(v, 0.f);
        }
        float upd = sb3;
#pragma unroll
        for (int k = 0; k < H; k++) {
            float y = sB2[k];
#pragma unroll
            for (int h = 0; h < H; h++) y = fmaf(z[h], sW2[h * H + k], y);
            upd = fmaf(fmaxf(y, 0.f), sW3[k], upd);
        }
        g_NW[i * N_U + j] = w + upd;
    }
}

// ---------------------------------------------------------------------------
// GEMM: out = relu(X[4096,1024] @ g_NW[1024,1024]), fp32 SIMT tiled.
// BM=BN=128, BK=16, 256 threads, 8x8 microtile.
// ---------------------------------------------------------------------------
#define BM 128
#define BN 128
#define BK 16
#define TM 8
#define TN 8

__global__ void __launch_bounds__(256) gemm_relu_kernel(const float* __restrict__ A,
                                                        float* __restrict__ out) {
    __shared__ float As[BK][BM + 4];   // padded: conflict-free transposed stores
    __shared__ float Bs[BK][BN];

    const float* __restrict__ B = g_NW;
    int bx = blockIdx.x;               // N tiles (8)
    int by = blockIdx.y;               // M tiles (32)
    int tid = threadIdx.x;
    int tx = tid & 15;                 // 0..15 -> N
    int ty = tid >> 4;                 // 0..15 -> M

    const float* Ablk = A + (by * BM) * N_U;
    const float* Bblk = B + bx * BN;

    float acc[TM][TN] = {};
    float ar[TM], br[TN];

    for (int k0 = 0; k0 < N_U; k0 += BK) {
        // Load A tile (128 x 16) transposed into As
#pragma unroll
        for (int t = 0; t < 2; t++) {
            int id = tid + t * 256;
            int arow = id >> 2;
            int ac   = (id & 3) * 4;
            float4 v = *(const float4*)(Ablk + arow * N_U + k0 + ac);
            As[ac + 0][arow] = v.x;
            As[ac + 1][arow] = v.y;
            As[ac + 2][arow] = v.z;
            As[ac + 3][arow] = v.w;
        }
        // Load B tile (16 x 128) straight
#pragma unroll
        for (int t = 0; t < 2; t++) {
            int id = tid + t * 256;
            int brow = id >> 5;
            int bc   = (id & 31) * 4;
            *(float4*)(&Bs[brow][bc]) = *(const float4*)(Bblk + (k0 + brow) * N_U + bc);
        }
        __syncthreads();

#pragma unroll
        for (int kk = 0; kk < BK; kk++) {
#pragma unroll
            for (int m = 0; m < TM; m++) ar[m] = As[kk][ty * TM + m];
#pragma unroll
            for (int n = 0; n < TN; n++) br[n] = Bs[kk][tx * TN + n];
#pragma unroll
            for (int m = 0; m < TM; m++)
#pragma unroll
                for (int n = 0; n < TN; n++)
                    acc[m][n] = fmaf(ar[m], br[n], acc[m][n]);
        }
        __syncthreads();
    }

#pragma unroll
    for (int m = 0; m < TM; m++) {
        int row = by * BM + ty * TM + m;
        int colbase = bx * BN + tx * TN;
#pragma unroll
        for (int n = 0; n < TN; n += 4) {
            float4 v;
            v.x = fmaxf(acc[m][n + 0], 0.f);
            v.y = fmaxf(acc[m][n + 1], 0.f);
            v.z = fmaxf(acc[m][n + 2], 0.f);
            v.w = fmaxf(acc[m][n + 3], 0.f);
            *(float4*)(out + row * N_U + colbase + n) = v;
        }
    }
}

// ---------------------------------------------------------------------------
// Row softmax in-place over d_out (4096 rows x 1024 cols); one block per row.
// ---------------------------------------------------------------------------
__global__ void __launch_bounds__(256) softmax_kernel(float* __restrict__ out) {
    __shared__ float redm[8];
    __shared__ float reds[8];
    __shared__ float bval[2];
    int row = blockIdx.x;
    int tid = threadIdx.x;
    int lane = tid & 31;
    int wid  = tid >> 5;

    float4 v = *(float4*)(out + row * N_U + tid * 4);

    float m = fmaxf(fmaxf(v.x, v.y), fmaxf(v.z, v.w));
#pragma unroll
    for (int o = 16; o > 0; o >>= 1) m = fmaxf(m, __shfl_xor_sync(0xffffffffu, m, o));
    if (lane == 0) redm[wid] = m;
    __syncthreads();
    if (tid == 0) {
        float t = redm[0];
#pragma unroll
        for (int i = 1; i < 8; i++) t = fmaxf(t, redm[i]);
        bval[0] = t;
    }
    __syncthreads();
    m = bval[0];

    v.x = expf(v.x - m);
    v.y = expf(v.y - m);
    v.z = expf(v.z - m);
    v.w = expf(v.w - m);

    float s = v.x + v.y + v.z + v.w;
#pragma unroll
    for (int o = 16; o > 0; o >>= 1) s += __shfl_xor_sync(0xffffffffu, s, o);
    if (lane == 0) reds[wid] = s;
    __syncthreads();
    if (tid == 0) {
        float t = 0.f;
#pragma unroll
        for (int i = 0; i < 8; i++) t += reds[i];
        bval[1] = 1.f / t;
    }
    __syncthreads();
    float inv = bval[1];

    v.x *= inv; v.y *= inv; v.z *= inv; v.w *= inv;
    *(float4*)(out + row * N_U + tid * 4) = v;
}

// ---------------------------------------------------------------------------
// Entry point
// inputs: 0:X 1:weight 2:hidden(unused, recomputed analytically) 3:W1 4:b1
//         5:W2 6:b2 7:W3 8:b3
// ---------------------------------------------------------------------------
extern "C" void kernel_launch(void* const* d_in, const int* in_sizes, int n_in,
                              void* d_out, int out_size) {
    const float* X      = (const float*)d_in[0];
    const float* weight = (const float*)d_in[1];
    const float* W1     = (const float*)d_in[3];
    const float* b1     = (const float*)d_in[4];
    const float* W2     = (const float*)d_in[5];
    const float* b2     = (const float*)d_in[6];
    const float* W3     = (const float*)d_in[7];
    const float* b3     = (const float*)d_in[8];
    float* out = (float*)d_out;

    colpart_kernel<<<dim3(8, 32), 128>>>(weight);
    colsum_kernel<<<4, 256>>>();
    rowsum_kernel<<<N_U, 256>>>(weight);
    precompute_kernel<<<9, 256>>>(W1, b1);
    mlp_kernel<<<N_U, 256>>>(weight, W2, b2, W3, b3);
    gemm_relu_kernel<<<dim3(N_U / BN, BATCH / BM), 256>>>(X, out);
    softmax_kernel<<<BATCH, 256>>>(out);
}

// round 3
// speedup vs baseline: 1.6991x; 1.6991x over previous
#include <cuda_runtime.h>
#include <cuda_bf16.h>
#include <cstdint>

// Problem constants
#define N_U   1024
#define BATCH 4096
#define H     10
#define INV1023 (1.0f / 1023.0f)
#define KTOT  3072          // 3 x 1024 (split-GEMM concatenated K)

// ---------------------------------------------------------------------------
// Scratch (device globals)
// ---------------------------------------------------------------------------
__device__ float g_colpart[32][N_U];
__device__ float g_colsum[N_U];
__device__ float g_rowsum[N_U];
__device__ float g_F[N_U][H];
__device__ float g_G[N_U][H];
__device__ float g_ACR[3][H];
__device__ __align__(256) float g_NW[N_U * N_U];                        // new_weight [k][n]

// Concatenated split operands (bf16 stored as ushort)
//   A_cat[m][k]: k<1024 -> bf16(X) ; 1024..2047 -> bf16(X) ; 2048..3071 -> bf16(X - bf16(X))
//   B_cat[n][k]: k<1024 -> bf16(NW[k][n]) ; 1024.. -> lo ; 2048.. -> hi
__device__ __align__(256) unsigned short g_Abf[BATCH * KTOT];           // 25.2 MB
__device__ __align__(256) unsigned short g_Bbf[N_U * KTOT];             //  6.3 MB

// ---------------------------------------------------------------------------
// Helpers
// ---------------------------------------------------------------------------
__device__ __forceinline__ uint32_t smem_u32(const void* p) {
    uint32_t a;
    asm("{ .reg .u64 t; cvta.to.shared.u64 t, %1; cvt.u32.u64 %0, t; }" : "=r"(a) : "l"(p));
    return a;
}
__device__ __forceinline__ unsigned short bf16u(float x) {
    return __bfloat16_as_ushort(__float2bfloat16_rn(x));
}
__device__ __forceinline__ float bf16f(float x) {
    return __bfloat162float(__float2bfloat16_rn(x));
}

#define CP_ASYNC16(dst, src) \
    asm volatile("cp.async.cg.shared.global [%0], [%1], 16;" :: "r"(dst), "l"(src))
#define CP_COMMIT() asm volatile("cp.async.commit_group;")
#define CP_WAIT(n)  asm volatile("cp.async.wait_group %0;" :: "n"(n))

#define LDMATRIX_X4(r0, r1, r2, r3, addr) \
    asm volatile("ldmatrix.sync.aligned.m8n8.x4.shared.b16 {%0,%1,%2,%3}, [%4];" \
        : "=r"(r0), "=r"(r1), "=r"(r2), "=r"(r3) : "r"(addr))

#define MMA_BF16(c0, c1, c2, c3, a0, a1, a2, a3, b0, b1) \
    asm volatile("mma.sync.aligned.m16n8k16.row.col.f32.bf16.bf16.f32 " \
        "{%0,%1,%2,%3}, {%4,%5,%6,%7}, {%8,%9}, {%0,%1,%2,%3};" \
        : "+f"(c0), "+f"(c1), "+f"(c2), "+f"(c3) \
        : "r"(a0), "r"(a1), "r"(a2), "r"(a3), "r"(b0), "r"(b1))

// ---------------------------------------------------------------------------
// Column sums (deterministic two-stage)
// ---------------------------------------------------------------------------
__global__ void __launch_bounds__(128) colpart_kernel(const float* __restrict__ W) {
    int col = blockIdx.x * 128 + threadIdx.x;
    int r0  = blockIdx.y * 32;
    float s = 0.f;
#pragma unroll
    for (int r = 0; r < 32; r++) s += W[(r0 + r) * N_U + col];
    g_colpart[blockIdx.y][col] = s;
}
__global__ void __launch_bounds__(256) colsum_kernel() {
    int col = blockIdx.x * 256 + threadIdx.x;
    float s = 0.f;
#pragma unroll
    for (int b = 0; b < 32; b++) s += g_colpart[b][col];
    g_colsum[col] = s;
}

// ---------------------------------------------------------------------------
// Row sums
// ---------------------------------------------------------------------------
__global__ void __launch_bounds__(256) rowsum_kernel(const float* __restrict__ W) {
    __shared__ float red[8];
    int row = blockIdx.x, tid = threadIdx.x;
    float4 v = *(const float4*)(W + row * N_U + tid * 4);
    float s = v.x + v.y + v.z + v.w;
#pragma unroll
    for (int o = 16; o > 0; o >>= 1) s += __shfl_xor_sync(0xffffffffu, s, o);
    if ((tid & 31) == 0) red[tid >> 5] = s;
    __syncthreads();
    if (tid == 0) {
        float t = 0.f;
#pragma unroll
        for (int i = 0; i < 8; i++) t += red[i];
        g_rowsum[row] = t;
    }
}

// ---------------------------------------------------------------------------
// Precompute F (per-i), G (per-j), coefficient tables
// ---------------------------------------------------------------------------
__global__ void precompute_kernel(const float* __restrict__ W1,
                                  const float* __restrict__ b1) {
    int idx = blockIdx.x * blockDim.x + threadIdx.x;
    if (idx < N_U) {
        int i = idx;
#pragma unroll
        for (int h = 0; h < H; h++) {
            float acc = 0.f;
#pragma unroll
            for (int t = 0; t < 10; t++) {
                float coef = W1[(3 + t) * H + h] + W1[(43 + t) * H + h]
                           - W1[(23 + t) * H + h] * INV1023;
                if ((i >> (9 - t)) & 1) acc += coef;
            }
            g_F[i][h] = acc;
        }
    } else if (idx < 2 * N_U) {
        int j = idx - N_U;
#pragma unroll
        for (int h = 0; h < H; h++) {
            float acc = b1[h];
#pragma unroll
            for (int s = 0; s < 10; s++) {
                float coef = W1[(13 + s) * H + h] + W1[(33 + s) * H + h]
                           - W1[(53 + s) * H + h] * INV1023;
                if ((j >> (9 - s)) & 1) acc += coef;
                acc += (512.f * INV1023) * (W1[(23 + s) * H + h] + W1[(53 + s) * H + h]);
            }
            g_G[j][h] = acc;
        }
    } else if (idx < 2 * N_U + H) {
        int h = idx - 2 * N_U;
        g_ACR[0][h] = W1[h] - (W1[H + h] + W1[2 * H + h]) * INV1023;
        g_ACR[1][h] = W1[H + h] * INV1023;
        g_ACR[2][h] = W1[2 * H + h] * INV1023;
    }
}

// ---------------------------------------------------------------------------
// Per-cell MLP -> g_NW
// ---------------------------------------------------------------------------
__global__ void __launch_bounds__(256) mlp_kernel(const float* __restrict__ W,
                                                  const float* __restrict__ W2,
                                                  const float* __restrict__ b2,
                                                  const float* __restrict__ W3,
                                                  const float* __restrict__ b3) {
    __shared__ float sW2[H * H], sB2[H], sW3[H], sF[H];
    __shared__ float sA[H], sC[H], sR[H];
    __shared__ float sb3;
    int tid = threadIdx.x, i = blockIdx.x;
    if (tid < H * H) sW2[tid] = W2[tid];
    if (tid < H) {
        sB2[tid] = b2[tid];
        sW3[tid] = W3[tid * 21];
        sF[tid]  = g_F[i][tid];
        sA[tid]  = g_ACR[0][tid];
        sC[tid]  = g_ACR[1][tid];
        sR[tid]  = g_ACR[2][tid];
    }
    if (tid == 0) sb3 = b3[0];
    __syncthreads();

    float rs = g_rowsum[i];
#pragma unroll
    for (int c = 0; c < 4; c++) {
        int j = c * 256 + tid;
        float w  = W[i * N_U + j];
        float cs = g_colsum[j];
        float z[H];
#pragma unroll
        for (int h = 0; h < H; h++) {
            float v = fmaf(sA[h], w, fmaf(sC[h], cs, fmaf(sR[h], rs, sF[h] + g_G[j][h])));
            z[h] = fmaxf(v, 0.f);
        }
        float upd = sb3;
#pragma unroll
        for (int k = 0; k < H; k++) {
            float y = sB2[k];
#pragma unroll
            for (int h = 0; h < H; h++) y = fmaf(z[h], sW2[h * H + k], y);
            upd = fmaf(fmaxf(y, 0.f), sW3[k], upd);
        }
        g_NW[i * N_U + j] = w + upd;
    }
}

// ---------------------------------------------------------------------------
// Transpose + split NW -> B_cat[n][k] (hi | lo | hi)
// ---------------------------------------------------------------------------
__global__ void __launch_bounds__(256) transpose_split_kernel() {
    __shared__ float tile[32][33];
    int bx = blockIdx.x, by = blockIdx.y;
    int tx = threadIdx.x, ty = threadIdx.y;           // 32 x 8
    int i0 = by * 32, j0 = bx * 32;
#pragma unroll
    for (int r = 0; r < 4; r++)
        tile[ty * 4 + r][tx] = g_NW[(i0 + ty * 4 + r) * N_U + j0 + tx];
    __syncthreads();
#pragma unroll
    for (int r = 0; r < 4; r++) {
        int j = j0 + ty * 4 + r;
        int i = i0 + tx;
        float v  = tile[tx][ty * 4 + r];
        float hi = bf16f(v);
        unsigned short h = bf16u(v);
        g_Bbf[j * KTOT + i]        = h;                 // seg0: hi
        g_Bbf[j * KTOT + 1024 + i] = bf16u(v - hi);     // seg1: lo
        g_Bbf[j * KTOT + 2048 + i] = h;                 // seg2: hi
    }
}

// ---------------------------------------------------------------------------
// Split X -> A_cat[m][k] (hi | hi | lo)
// ---------------------------------------------------------------------------
__global__ void __launch_bounds__(256) split_x_kernel(const float* __restrict__ X) {
    int gid = blockIdx.x * 256 + threadIdx.x;         // 1M threads, 4 elems each
    int idx = gid * 4;
    int m = idx >> 10;
    int k = idx & 1023;
    float4 v = *(const float4*)(X + idx);
    uint32_t hi01 = (uint32_t)bf16u(v.x) | ((uint32_t)bf16u(v.y) << 16);
    uint32_t hi23 = (uint32_t)bf16u(v.z) | ((uint32_t)bf16u(v.w) << 16);
    uint32_t lo01 = (uint32_t)bf16u(v.x - bf16f(v.x)) | ((uint32_t)bf16u(v.y - bf16f(v.y)) << 16);
    uint32_t lo23 = (uint32_t)bf16u(v.z - bf16f(v.z)) | ((uint32_t)bf16u(v.w - bf16f(v.w)) << 16);
    unsigned short* base = g_Abf + (size_t)m * KTOT + k;
    *(uint2*)(base)        = make_uint2(hi01, hi23);
    *(uint2*)(base + 1024) = make_uint2(hi01, hi23);
    *(uint2*)(base + 2048) = make_uint2(lo01, lo23);
}

// ---------------------------------------------------------------------------
// GEMM: out = relu( A_cat @ B_cat^T ), bf16 mma.sync, 4-stage cp.async pipe.
// BM=128, BN=256, BK=32, 512 threads (16 warps, 4x4).
// smem rows padded to 40 bf16 (80B) -> conflict-free ldmatrix.
// ---------------------------------------------------------------------------
#define BM 128
#define BN 256
#define BK 32
#define STAGES 4
#define A_ROW 40                         // bf16 elems per padded smem row
#define A_BYTES (BM * A_ROW * 2)         // 10240
#define B_BYTES (BN * A_ROW * 2)         // 20480
#define STAGE_BYTES (A_BYTES + B_BYTES)  // 30720
#define SMEM_GEMM (STAGES * STAGE_BYTES) // 122880

__global__ void __launch_bounds__(512, 1) gemm_mma_kernel(float* __restrict__ out) {
    extern __shared__ char smem[];
    uint32_t sb = smem_u32(smem);
    int tid  = threadIdx.x;
    int wid  = tid >> 5;
    int lane = tid & 31;

    int mt = blockIdx.x & 31;            // 32 m-tiles
    int nt = blockIdx.x >> 5;            // 4 n-tiles
    int mw = wid & 3;                    // warp m (4)
    int nw = wid >> 2;                   // warp n (4)

    const unsigned short* Ag = g_Abf + (size_t)(mt * BM) * KTOT;
    const unsigned short* Bg = g_Bbf + (size_t)(nt * BN) * KTOT;

    // per-thread cp.async coords
    int a_row = tid >> 2;                // 0..127
    int a_chk = (tid & 3) * 8;           // bf16 elems
    int b_row0 = tid >> 2;               // 0..127 (first half)
    int b_chk  = (tid & 3) * 8;

    float c[2][8][4];
#pragma unroll
    for (int i = 0; i < 2; i++)
#pragma unroll
        for (int j = 0; j < 8; j++)
#pragma unroll
            for (int q = 0; q < 4; q++) c[i][j][q] = 0.f;

    const int ITERS = KTOT / BK;         // 96

    auto load_stage = [&](int it, int st) {
        int k0 = it * BK;
        uint32_t abase = sb + st * STAGE_BYTES;
        uint32_t bbase = abase + A_BYTES;
        CP_ASYNC16(abase + a_row * (A_ROW * 2) + a_chk * 2,
                   (const char*)(Ag + (size_t)a_row * KTOT + k0 + a_chk));
        CP_ASYNC16(bbase + b_row0 * (A_ROW * 2) + b_chk * 2,
                   (const char*)(Bg + (size_t)b_row0 * KTOT + k0 + b_chk));
        CP_ASYNC16(bbase + (b_row0 + 128) * (A_ROW * 2) + b_chk * 2,
                   (const char*)(Bg + (size_t)(b_row0 + 128) * KTOT + k0 + b_chk));
    };

#pragma unroll
    for (int s = 0; s < STAGES - 1; s++) {
        load_stage(s, s);
        CP_COMMIT();
    }

    // ldmatrix lane addressing (constant per thread)
    int lrow = lane & 15;
    int lcol = (lane >> 4) * 16;         // bytes within 32B k-chunk

    for (int i = 0; i < ITERS; i++) {
        CP_WAIT(2);
        __syncthreads();

        int nx = i + STAGES - 1;
        if (nx < ITERS) load_stage(nx, nx & (STAGES - 1));
        CP_COMMIT();

        int st = i & (STAGES - 1);
        uint32_t abase = sb + st * STAGE_BYTES;
        uint32_t bbase = abase + A_BYTES;

#pragma unroll
        for (int ks = 0; ks < 2; ks++) {
            uint32_t a0[4], a1[4];
            LDMATRIX_X4(a0[0], a0[1], a0[2], a0[3],
                abase + (mw * 32 + 0 + lrow) * (A_ROW * 2) + ks * 32 + lcol);
            LDMATRIX_X4(a1[0], a1[1], a1[2], a1[3],
                abase + (mw * 32 + 16 + lrow) * (A_ROW * 2) + ks * 32 + lcol);
            uint32_t b[8][2];
#pragma unroll
            for (int g = 0; g < 4; g++) {
                uint32_t r0, r1, r2, r3;
                LDMATRIX_X4(r0, r1, r2, r3,
                    bbase + (nw * 64 + g * 16 + lrow) * (A_ROW * 2) + ks * 32 + lcol);
                b[2 * g][0] = r0;  b[2 * g][1] = r2;
                b[2 * g + 1][0] = r1;  b[2 * g + 1][1] = r3;
            }
#pragma unroll
            for (int nf = 0; nf < 8; nf++) {
                MMA_BF16(c[0][nf][0], c[0][nf][1], c[0][nf][2], c[0][nf][3],
                         a0[0], a0[1], a0[2], a0[3], b[nf][0], b[nf][1]);
                MMA_BF16(c[1][nf][0], c[1][nf][1], c[1][nf][2], c[1][nf][3],
                         a1[0], a1[1], a1[2], a1[3], b[nf][0], b[nf][1]);
            }
        }
        __syncthreads();
    }

    // Epilogue: relu + store
    int row0 = mt * BM + mw * 32 + (lane >> 2);
    int col0 = nt * BN + nw * 64 + (lane & 3) * 2;
#pragma unroll
    for (int mf = 0; mf < 2; mf++) {
#pragma unroll
        for (int nf = 0; nf < 8; nf++) {
            int r = row0 + mf * 16;
            int cc = col0 + nf * 8;
            float2 v0, v1;
            v0.x = fmaxf(c[mf][nf][0], 0.f);
            v0.y = fmaxf(c[mf][nf][1], 0.f);
            v1.x = fmaxf(c[mf][nf][2], 0.f);
            v1.y = fmaxf(c[mf][nf][3], 0.f);
            *(float2*)(out + (size_t)r * N_U + cc)       = v0;
            *(float2*)(out + (size_t)(r + 8) * N_U + cc) = v1;
        }
    }
}

// ---------------------------------------------------------------------------
// Row softmax in-place
// ---------------------------------------------------------------------------
__global__ void __launch_bounds__(256) softmax_kernel(float* __restrict__ out) {
    __shared__ float redm[8];
    __shared__ float reds[8];
    __shared__ float bval[2];
    int row = blockIdx.x, tid = threadIdx.x;
    int lane = tid & 31, wid = tid >> 5;

    float4 v = *(float4*)(out + row * N_U + tid * 4);
    float m = fmaxf(fmaxf(v.x, v.y), fmaxf(v.z, v.w));
#pragma unroll
    for (int o = 16; o > 0; o >>= 1) m = fmaxf(m, __shfl_xor_sync(0xffffffffu, m, o));
    if (lane == 0) redm[wid] = m;
    __syncthreads();
    if (tid == 0) {
        float t = redm[0];
#pragma unroll
        for (int i = 1; i < 8; i++) t = fmaxf(t, redm[i]);
        bval[0] = t;
    }
    __syncthreads();
    m = bval[0];
    v.x = expf(v.x - m); v.y = expf(v.y - m);
    v.z = expf(v.z - m); v.w = expf(v.w - m);
    float s = v.x + v.y + v.z + v.w;
#pragma unroll
    for (int o = 16; o > 0; o >>= 1) s += __shfl_xor_sync(0xffffffffu, s, o);
    if (lane == 0) reds[wid] = s;
    __syncthreads();
    if (tid == 0) {
        float t = 0.f;
#pragma unroll
        for (int i = 0; i < 8; i++) t += reds[i];
        bval[1] = 1.f / t;
    }
    __syncthreads();
    float inv = bval[1];
    v.x *= inv; v.y *= inv; v.z *= inv; v.w *= inv;
    *(float4*)(out + row * N_U + tid * 4) = v;
}

// ---------------------------------------------------------------------------
// Entry point
// ---------------------------------------------------------------------------
extern "C" void kernel_launch(void* const* d_in, const int* in_sizes, int n_in,
                              void* d_out, int out_size) {
    const float* X      = (const float*)d_in[0];
    const float* weight = (const float*)d_in[1];
    const float* W1     = (const float*)d_in[3];
    const float* b1     = (const float*)d_in[4];
    const float* W2     = (const float*)d_in[5];
    const float* b2     = (const float*)d_in[6];
    const float* W3     = (const float*)d_in[7];
    const float* b3     = (const float*)d_in[8];
    float* out = (float*)d_out;

    static bool attr_done = false;
    if (!attr_done) {
        cudaFuncSetAttribute(gemm_mma_kernel,
                             cudaFuncAttributeMaxDynamicSharedMemorySize, SMEM_GEMM);
        attr_done = true;
    }

    colpart_kernel<<<dim3(8, 32), 128>>>(weight);
    colsum_kernel<<<4, 256>>>();
    rowsum_kernel<<<N_U, 256>>>(weight);
    precompute_kernel<<<9, 256>>>(W1, b1);
    mlp_kernel<<<N_U, 256>>>(weight, W2, b2, W3, b3);
    transpose_split_kernel<<<dim3(32, 32), dim3(32, 8)>>>();
    split_x_kernel<<<BATCH * N_U / 1024, 256>>>(X);
    gemm_mma_kernel<<<128, 512, SMEM_GEMM>>>(out);
    softmax_kernel<<<BATCH, 256>>>(out);
}